// round 1
// baseline (speedup 1.0000x reference)
#include <cuda_runtime.h>
#include <math.h>

// Problem constants
#define B_ 32768
#define D_ 256
#define N_ 8192

// GEMM tiling
#define BM 128
#define BN 128
#define BK 16
#define TM 8
#define TN 8

#define EPI_BLOCKS (B_ / 8)   // 4096 blocks, 8 warps (rows) per block

// Scratch (no allocations allowed; __device__ globals are the sanctioned path)
__device__ float g_cbn[N_ * D_];      // L2-normalized codebook (8 MB)
__device__ int   g_bidx[B_];          // argmax index per row
__device__ float g_partial[EPI_BLOCKS]; // per-block loss partials

// ---------------------------------------------------------------------------
// Kernel 1: normalize codebook rows: cbn = e / max(||e||, 1e-12)
// One block (256 threads) per code row (D_ == 256).
// ---------------------------------------------------------------------------
__global__ void normalize_cb_kernel(const float* __restrict__ E) {
    int n = blockIdx.x;
    int t = threadIdx.x;
    float v = E[(size_t)n * D_ + t];
    float s = v * v;
    #pragma unroll
    for (int o = 16; o; o >>= 1) s += __shfl_xor_sync(0xffffffffu, s, o);
    __shared__ float red[8];
    int w = t >> 5, l = t & 31;
    if (l == 0) red[w] = s;
    __syncthreads();
    if (t == 0) {
        float tot = 0.f;
        #pragma unroll
        for (int i = 0; i < 8; i++) tot += red[i];
        red[0] = fmaxf(sqrtf(tot), 1e-12f);
    }
    __syncthreads();
    g_cbn[(size_t)n * D_ + t] = v / red[0];
}

// ---------------------------------------------------------------------------
// Kernel 2: fused GEMM + per-row running argmax.
// sim'(b,n) = x_b . cbn_n   (row norm of x is a positive scale -> argmax-safe)
// Classic SGEMM tiling: BM=BN=128, BK=16, 8x8 per-thread microtile.
// Tie-break: first occurrence (lowest n), matching jnp.argmin.
// ---------------------------------------------------------------------------
__global__ __launch_bounds__(256, 2)
void gemm_argmax_kernel(const float* __restrict__ X) {
    __shared__ float As[BK][BM];
    __shared__ float Bs[BK][BN];
    __shared__ float sv[BM][16];
    __shared__ int   si[BM][16];

    const int tid = threadIdx.x;
    const int tx = tid & 15;        // column group
    const int ty = tid >> 4;        // row group
    const int rowBase = blockIdx.x * BM;

    float bestv[TM];
    int   besti[TM];
    #pragma unroll
    for (int i = 0; i < TM; i++) { bestv[i] = -3.4e38f; besti[i] = 0; }

    for (int n0 = 0; n0 < N_; n0 += BN) {
        float acc[TM][TN];
        #pragma unroll
        for (int i = 0; i < TM; i++)
            #pragma unroll
            for (int j = 0; j < TN; j++) acc[i][j] = 0.f;

        for (int k0 = 0; k0 < D_; k0 += BK) {
            // Cooperative loads: 128 rows x 16 k each for A and B tiles.
            // 512 float4 per tile, 256 threads -> 2 float4 each.
            #pragma unroll
            for (int r = 0; r < 2; r++) {
                int v  = tid + r * 256;
                int m  = v >> 2;            // 0..127
                int kq = (v & 3) * 4;       // 0,4,8,12
                float4 a = *(const float4*)(&X[(size_t)(rowBase + m) * D_ + k0 + kq]);
                As[kq + 0][m] = a.x; As[kq + 1][m] = a.y;
                As[kq + 2][m] = a.z; As[kq + 3][m] = a.w;
                float4 b = *(const float4*)(&g_cbn[(size_t)(n0 + m) * D_ + k0 + kq]);
                Bs[kq + 0][m] = b.x; Bs[kq + 1][m] = b.y;
                Bs[kq + 2][m] = b.z; Bs[kq + 3][m] = b.w;
            }
            __syncthreads();
            #pragma unroll
            for (int k = 0; k < BK; k++) {
                float ar[TM], br[TN];
                #pragma unroll
                for (int i = 0; i < TM; i++) ar[i] = As[k][ty * TM + i];
                #pragma unroll
                for (int j = 0; j < TN; j++) br[j] = Bs[k][tx * TN + j];
                #pragma unroll
                for (int i = 0; i < TM; i++)
                    #pragma unroll
                    for (int j = 0; j < TN; j++)
                        acc[i][j] = fmaf(ar[i], br[j], acc[i][j]);
            }
            __syncthreads();
        }
        // Fold this BN tile into the running argmax (ascending j keeps
        // first-occurrence semantics within this thread's columns).
        #pragma unroll
        for (int i = 0; i < TM; i++) {
            #pragma unroll
            for (int j = 0; j < TN; j++) {
                float v = acc[i][j];
                if (v > bestv[i]) { bestv[i] = v; besti[i] = n0 + tx * TN + j; }
            }
        }
    }

    // Cross-thread reduction: 16 column-group threads per row.
    #pragma unroll
    for (int i = 0; i < TM; i++) {
        sv[ty * TM + i][tx] = bestv[i];
        si[ty * TM + i][tx] = besti[i];
    }
    __syncthreads();
    if (tid < BM) {
        float bv = -3.4e38f;
        int   bi = 0x7fffffff;
        #pragma unroll
        for (int t = 0; t < 16; t++) {
            float v = sv[tid][t];
            int  ii = si[tid][t];
            if (v > bv || (v == bv && ii < bi)) { bv = v; bi = ii; }
        }
        g_bidx[rowBase + tid] = bi;
    }
}

// ---------------------------------------------------------------------------
// Kernel 3: epilogue. One warp per row.
// scalar = (x.cv)/(cv.cv + 1e-8); x_q = x + (scalar*cv - x);
// commit = (scalar*dot)/(max(|scalar|*|cv|,1e-8)*max(|x|,1e-8))
// Output layout (fp32): [x_q (B*D) | loss (1) | indices (B) | scalar (B)]
// ---------------------------------------------------------------------------
__global__ void epilogue_kernel(const float* __restrict__ X,
                                const float* __restrict__ E,
                                float* __restrict__ out) {
    const int gw   = (blockIdx.x * blockDim.x + threadIdx.x) >> 5;
    const int lane = threadIdx.x & 31;
    __shared__ float wsum[8];
    float contrib = 0.f;

    if (gw < B_) {
        const int b   = gw;
        const int idx = g_bidx[b];
        const float4* xr = (const float4*)(X + (size_t)b * D_);
        const float4* cr = (const float4*)(E + (size_t)idx * D_);
        float dot = 0.f, nsq = 0.f, xsq = 0.f;
        float4 xv[2], cv[2];
        #pragma unroll
        for (int r = 0; r < 2; r++) {
            int q = lane + r * 32;          // 64 float4 per row
            xv[r] = xr[q];
            cv[r] = cr[q];
            dot += xv[r].x * cv[r].x + xv[r].y * cv[r].y
                 + xv[r].z * cv[r].z + xv[r].w * cv[r].w;
            nsq += cv[r].x * cv[r].x + cv[r].y * cv[r].y
                 + cv[r].z * cv[r].z + cv[r].w * cv[r].w;
            xsq += xv[r].x * xv[r].x + xv[r].y * xv[r].y
                 + xv[r].z * xv[r].z + xv[r].w * xv[r].w;
        }
        #pragma unroll
        for (int o = 16; o; o >>= 1) {
            dot += __shfl_xor_sync(0xffffffffu, dot, o);
            nsq += __shfl_xor_sync(0xffffffffu, nsq, o);
            xsq += __shfl_xor_sync(0xffffffffu, xsq, o);
        }
        const float scalar = dot / (nsq + 1e-8f);
        float4* orow = (float4*)(out + (size_t)b * D_);
        #pragma unroll
        for (int r = 0; r < 2; r++) {
            int q = lane + r * 32;
            float4 o;
            o.x = xv[r].x + (scalar * cv[r].x - xv[r].x);
            o.y = xv[r].y + (scalar * cv[r].y - xv[r].y);
            o.z = xv[r].z + (scalar * cv[r].z - xv[r].z);
            o.w = xv[r].w + (scalar * cv[r].w - xv[r].w);
            orow[q] = o;
        }
        if (lane == 0) {
            out[(size_t)B_ * D_ + 1 + b]       = (float)idx;
            out[(size_t)B_ * D_ + 1 + B_ + b]  = scalar;
            const float nproj = fabsf(scalar) * sqrtf(nsq);
            const float nx    = sqrtf(xsq);
            const float commit = (scalar * dot) /
                (fmaxf(nproj, 1e-8f) * fmaxf(nx, 1e-8f));
            contrib = 1.f - commit;
        }
    }

    // Deterministic per-block partial (8 warps, fixed order)
    const int w = threadIdx.x >> 5;
    if (lane == 0) wsum[w] = contrib;
    __syncthreads();
    if (threadIdx.x == 0) {
        float s = 0.f;
        #pragma unroll
        for (int i = 0; i < 8; i++) s += wsum[i];
        g_partial[blockIdx.x] = s;
    }
}

// ---------------------------------------------------------------------------
// Kernel 4: deterministic final loss reduction (double accumulation).
// ---------------------------------------------------------------------------
__global__ void loss_kernel(float* __restrict__ out) {
    __shared__ double red[256];
    const int t = threadIdx.x;
    double s = 0.0;
    for (int i = t; i < EPI_BLOCKS; i += 256) s += (double)g_partial[i];
    red[t] = s;
    __syncthreads();
    for (int o = 128; o; o >>= 1) {
        if (t < o) red[t] += red[t + o];
        __syncthreads();
    }
    if (t == 0) out[(size_t)B_ * D_] = (float)(0.25 * red[0] / (double)B_);
}

// ---------------------------------------------------------------------------
extern "C" void kernel_launch(void* const* d_in, const int* in_sizes, int n_in,
                              void* d_out, int out_size) {
    const float* X = (const float*)d_in[0];   // (32768, 256) fp32
    const float* E = (const float*)d_in[1];   // (8192, 256) fp32
    float* out = (float*)d_out;

    normalize_cb_kernel<<<N_, 256>>>(E);
    gemm_argmax_kernel<<<B_ / BM, 256>>>(X);
    epilogue_kernel<<<EPI_BLOCKS, 256>>>(X, E, out);
    loss_kernel<<<1, 256>>>(out);
}

// round 6
// speedup vs baseline: 3.2376x; 3.2376x over previous
#include <cuda_runtime.h>
#include <cuda_bf16.h>
#include <math.h>
#include <stdint.h>

// ---------------------------------------------------------------------------
// Problem constants
// ---------------------------------------------------------------------------
#define B_ 32768
#define D_ 256
#define N_ 8192

#define MT 128              // M rows per CTA
#define NTILE 128           // N cols per B stream block
#define NTILES (N_ / NTILE) // 64
#define MTILES (B_ / MT)    // 256
#define KST 4               // B smem ring stages

#define BLK 16384           // one k64 block: 128 rows x 64 bf16 (SW128-swizzled)

// dynamic smem layout
#define SM_AFULL  8
#define SM_KFULL  16        // 4 x 8B  (16..47)
#define SM_KEMPTY 48        // 4 x 8B  (48..79)
#define SM_SV2    128       // uint4[128][2] = 4KB
#define SM_A      8192      // 8 x 16KB = 128KB  (hi0-3, lo0-3)
#define SM_B      (SM_A + 8 * BLK)       // 139264
#define SMEM_TOTAL (SM_B + KST * BLK)    // 204800

#define EPI_BLOCKS (B_ / 8)

// ---------------------------------------------------------------------------
// Global scratch
// ---------------------------------------------------------------------------
__device__ __align__(16) uint8_t g_Asw[(size_t)MTILES * 8 * BLK];  // 32 MB
__device__ __align__(16) uint8_t g_Bsw[(size_t)NTILES * 8 * BLK];  // 8 MB
__device__ int2  g_top2[B_];
__device__ float g_partial[EPI_BLOCKS];

// ---------------------------------------------------------------------------
// PTX helpers (family-wide sm_90 features only — NO tcgen05)
// ---------------------------------------------------------------------------
__device__ __forceinline__ uint32_t smem_u32(const void* p) {
    uint32_t a;
    asm("{ .reg .u64 t; cvta.to.shared.u64 t, %1; cvt.u32.u64 %0, t; }"
        : "=r"(a) : "l"(p));
    return a;
}
__device__ __forceinline__ uint32_t elect_one() {
    uint32_t pred;
    asm volatile("{\n\t.reg .pred p;\n\telect.sync _|p, 0xFFFFFFFF;\n\t"
                 "selp.b32 %0, 1, 0, p;\n\t}" : "=r"(pred));
    return pred;
}
#define MBAR_INIT(addr, cnt) \
    asm volatile("mbarrier.init.shared.b64 [%0], %1;" :: "r"(addr), "r"(cnt) : "memory")
#define MBAR_EXPECT_TX(addr, bytes) \
    asm volatile("mbarrier.arrive.expect_tx.shared.b64 _, [%0], %1;" \
                 :: "r"(addr), "r"(bytes) : "memory")
#define MBAR_ARRIVE(addr) \
    asm volatile("mbarrier.arrive.shared.b64 _, [%0];" :: "r"(addr) : "memory")
#define MBAR_WAIT(addr, ph) do {                                              \
    uint32_t _m = (addr), _p = (ph), _d;                                      \
    asm volatile("{\n\t.reg .pred p;\n\t"                                     \
        "mbarrier.try_wait.parity.acquire.cta.shared::cta.b64 p, [%1], %2;\n\t" \
        "selp.b32 %0, 1, 0, p;\n\t}" : "=r"(_d) : "r"(_m), "r"(_p) : "memory");\
    if (!_d) {                                                                \
        asm volatile("{\n\t.reg .pred P1;\n\t"                                \
            "WL_%=:\n\t"                                                      \
            "mbarrier.try_wait.parity.acquire.cta.shared::cta.b64 P1, [%0], %1, 0x989680;\n\t" \
            "@P1 bra.uni WD_%=;\n\t"                                          \
            "bra.uni WL_%=;\n\t"                                              \
            "WD_%=:\n\t}" :: "r"(_m), "r"(_p) : "memory");                    \
    } } while (0)
#define BULK_G2S(dst, src, bytes, mbar) \
    asm volatile("cp.async.bulk.shared::cta.global.mbarrier::complete_tx::bytes " \
                 "[%0], [%1], %2, [%3];" \
                 :: "r"(dst), "l"(src), "r"(bytes), "r"(mbar) : "memory")
#define LDSM_X4(r0, r1, r2, r3, a) \
    asm volatile("ldmatrix.sync.aligned.m8n8.x4.shared.b16 {%0,%1,%2,%3}, [%4];" \
        : "=r"(r0), "=r"(r1), "=r"(r2), "=r"(r3) : "r"(a))
#define MMA_BF16(d, a0, a1, a2, a3, b0, b1) \
    asm volatile("mma.sync.aligned.m16n8k16.row.col.f32.bf16.bf16.f32 " \
        "{%0,%1,%2,%3}, {%4,%5,%6,%7}, {%8,%9}, {%0,%1,%2,%3};" \
        : "+f"((d)[0]), "+f"((d)[1]), "+f"((d)[2]), "+f"((d)[3]) \
        : "r"(a0), "r"(a1), "r"(a2), "r"(a3), "r"(b0), "r"(b1))

union Pack8 { __nv_bfloat16 h[8]; uint4 v; };

// ---------------------------------------------------------------------------
// Kernel 1: split X into bf16 hi/lo, pre-swizzled SW128 16KB blocks.
// Block (mtile*8 + kc) = hi, (mtile*8 + 4 + kc) = lo; element (m, col) at
// swizzle(m*128 + col*2), 128B rows of 64 bf16.
// ---------------------------------------------------------------------------
__global__ void split_x_kernel(const float* __restrict__ X) {
    int g = blockIdx.x * 256 + threadIdx.x;
    int b  = g >> 5;
    int cg = g & 31;
    const float4* xp = (const float4*)(X + (size_t)b * D_ + cg * 8);
    float4 x0 = xp[0], x1 = xp[1];
    float xs[8] = {x0.x, x0.y, x0.z, x0.w, x1.x, x1.y, x1.z, x1.w};
    Pack8 hi, lo;
    #pragma unroll
    for (int i = 0; i < 8; i++) {
        __nv_bfloat16 h = __float2bfloat16(xs[i]);
        hi.h[i] = h;
        lo.h[i] = __float2bfloat16(xs[i] - __bfloat162float(h));
    }
    int mtile = b >> 7, m = b & 127, kc = cg >> 3;
    uint32_t off = m * 128 + (cg & 7) * 16;
    uint32_t sw = off ^ ((off >> 3) & 0x70);
    *(uint4*)(g_Asw + ((size_t)(mtile * 8 + kc)) * BLK + sw) = hi.v;
    *(uint4*)(g_Asw + ((size_t)(mtile * 8 + 4 + kc)) * BLK + sw) = lo.v;
}

// ---------------------------------------------------------------------------
// Kernel 2: normalize codebook rows, split to bf16 hi/lo pre-swizzled blocks.
// Block (ntile*8 + kc) = hi, (+4) = lo; 128 n-rows x 64 bf16 each.
// ---------------------------------------------------------------------------
__global__ void split_cb_kernel(const float* __restrict__ E) {
    int n = blockIdx.x;
    int t = threadIdx.x;
    float v = E[(size_t)n * D_ + t];
    float s = v * v;
    #pragma unroll
    for (int o = 16; o; o >>= 1) s += __shfl_xor_sync(0xffffffffu, s, o);
    __shared__ float red[8];
    __shared__ float sv[256];
    if ((t & 31) == 0) red[t >> 5] = s;
    __syncthreads();
    if (t == 0) {
        float tot = 0.f;
        #pragma unroll
        for (int i = 0; i < 8; i++) tot += red[i];
        red[0] = fmaxf(sqrtf(tot), 1e-12f);
    }
    __syncthreads();
    sv[t] = v / red[0];
    __syncthreads();
    if (t < 64) {
        int cg = t & 31;
        int isLo = t >> 5;
        Pack8 u;
        #pragma unroll
        for (int i = 0; i < 8; i++) {
            float f = sv[cg * 8 + i];
            __nv_bfloat16 h = __float2bfloat16(f);
            u.h[i] = isLo ? __float2bfloat16(f - __bfloat162float(h)) : h;
        }
        int nc = n >> 7, r = n & 127, kc = cg >> 3;
        uint32_t off = r * 128 + (cg & 7) * 16;
        uint32_t sw = off ^ ((off >> 3) & 0x70);
        *(uint4*)(g_Bsw + ((size_t)(nc * 8 + kc + (isLo ? 4 : 0))) * BLK + sw) = u.v;
    }
}

// ---------------------------------------------------------------------------
// One k64 step: 4x k16 {ldmatrix A (2 m-tiles), ldmatrix B (4 pairs), 16 mma}.
// ---------------------------------------------------------------------------
__device__ __forceinline__ void kstep(uint32_t aBase, uint32_t bBase,
                                      float acc[2][8][4],
                                      int a_kbh, int b_rowoff, int b_kbh, int sx) {
    #pragma unroll
    for (int q = 0; q < 4; q++) {
        uint32_t a0[4], a1[4];
        uint32_t aAddr = aBase + ((q * 32 + a_kbh) ^ sx);
        LDSM_X4(a0[0], a0[1], a0[2], a0[3], aAddr);
        LDSM_X4(a1[0], a1[1], a1[2], a1[3], aAddr + 16 * 128);
        uint32_t bb[4][4];
        #pragma unroll
        for (int p = 0; p < 4; p++) {
            uint32_t bAddr = bBase + (p * 16 + b_rowoff) * 128 + ((q * 32 + b_kbh) ^ sx);
            LDSM_X4(bb[p][0], bb[p][1], bb[p][2], bb[p][3], bAddr);
        }
        #pragma unroll
        for (int nt = 0; nt < 8; nt++) {
            uint32_t bf0 = bb[nt >> 1][(nt & 1) * 2];
            uint32_t bf1 = bb[nt >> 1][(nt & 1) * 2 + 1];
            MMA_BF16(acc[0][nt], a0[0], a0[1], a0[2], a0[3], bf0, bf1);
            MMA_BF16(acc[1][nt], a1[0], a1[1], a1[2], a1[3], bf0, bf1);
        }
    }
}

__device__ __forceinline__ void merge_top2(float& v1, int& i1, float& v2, int& i2,
                                           float w1, int k1, float w2, int k2) {
    if (w1 > v1 || (w1 == v1 && k1 < i1)) {
        if (v1 > w2 || (v1 == w2 && i1 < k2)) { v2 = v1; i2 = i1; }
        else                                   { v2 = w2; i2 = k2; }
        v1 = w1; i1 = k1;
    } else if (w1 > v2 || (w1 == v2 && k1 < i2)) {
        v2 = w1; i2 = k1;
    }
}

// ---------------------------------------------------------------------------
// Kernel 3: HMMA GEMM + per-row top-2 argmax.
// sim(b,n) = hi_x.hi_e + lo_x.hi_e + hi_x.lo_e  (bf16 mma, fp32 accum)
// 288 threads: warps 0-7 compute (4x2 warp grid, 32x64 tiles); warp 8 produces.
// ---------------------------------------------------------------------------
__global__ __launch_bounds__(288, 1) void mma_argmax_kernel() {
    extern __shared__ char smem[];
    const uint32_t sb = smem_u32(smem);
    uint4* sv2 = (uint4*)(smem + SM_SV2);
    const int tid = threadIdx.x, wid = tid >> 5, lane = tid & 31;

    if (tid == 0) {
        MBAR_INIT(sb + SM_AFULL, 1);
        #pragma unroll
        for (int s = 0; s < KST; s++) {
            MBAR_INIT(sb + SM_KFULL + 8 * s, 1);
            MBAR_INIT(sb + SM_KEMPTY + 8 * s, 8);
        }
        asm volatile("fence.proxy.async.shared::cta;" ::: "memory");
    }
    __syncthreads();

    if (wid == 8) {
        // ---- producer: A once (8 x 16KB), then B ring (hi0-3, lo0-3 / tile) ----
        if (elect_one()) {
            MBAR_EXPECT_TX(sb + SM_AFULL, 8 * BLK);
            #pragma unroll
            for (int blk = 0; blk < 8; blk++)
                BULK_G2S(sb + SM_A + blk * BLK,
                         g_Asw + ((size_t)blockIdx.x * 8 + blk) * BLK,
                         BLK, sb + SM_AFULL);
            int ks = 0, kph = 1;
            for (int c = 0; c < NTILES; c++) {
                for (int t = 0; t < 8; t++) {
                    MBAR_WAIT(sb + SM_KEMPTY + 8 * ks, kph);
                    MBAR_EXPECT_TX(sb + SM_KFULL + 8 * ks, BLK);
                    BULK_G2S(sb + SM_B + ks * BLK,
                             g_Bsw + ((size_t)c * 8 + t) * BLK,
                             BLK, sb + SM_KFULL + 8 * ks);
                    if (++ks == KST) { ks = 0; kph ^= 1; }
                }
            }
        }
    } else {
        // ---- compute warps ----
        const int wm = wid >> 1, wn = wid & 1;
        const int sx = (lane & 7) * 16;
        const int a_row0 = lane & 15;
        const int a_kbh = (lane >> 4) * 16;
        const int b_rowoff = ((lane >> 4) & 1) * 8 + (lane & 7);
        const int b_kbh = ((lane >> 3) & 1) * 16;
        const uint32_t aWarp = sb + SM_A + wm * 4096 + a_row0 * 128;
        const int g = lane >> 2, cq = lane & 3;

        float tv1[4], tv2[4];
        int ti1[4], ti2[4];
        #pragma unroll
        for (int s = 0; s < 4; s++) { tv1[s] = -3.4e38f; tv2[s] = -3.4e38f;
                                      ti1[s] = 0; ti2[s] = 0x7fffffff; }

        MBAR_WAIT(sb + SM_AFULL, 0);

        int ks = 0, kph = 0;
        for (int c = 0; c < NTILES; c++) {
            float acc[2][8][4];
            #pragma unroll
            for (int mt = 0; mt < 2; mt++)
                #pragma unroll
                for (int nt = 0; nt < 8; nt++)
                    #pragma unroll
                    for (int r = 0; r < 4; r++) acc[mt][nt][r] = 0.f;

            #pragma unroll 1
            for (int j = 0; j < 4; j++) {     // B = hi_j: A = hi_j then lo_j
                MBAR_WAIT(sb + SM_KFULL + 8 * ks, kph);
                const uint32_t bBase = sb + SM_B + ks * BLK + wn * 8192;
                kstep(aWarp + j * BLK, bBase, acc, a_kbh, b_rowoff, b_kbh, sx);
                kstep(aWarp + (4 + j) * BLK, bBase, acc, a_kbh, b_rowoff, b_kbh, sx);
                if (lane == 0) MBAR_ARRIVE(sb + SM_KEMPTY + 8 * ks);
                if (++ks == KST) { ks = 0; kph ^= 1; }
            }
            #pragma unroll 1
            for (int j = 0; j < 4; j++) {     // B = lo_j: A = hi_j
                MBAR_WAIT(sb + SM_KFULL + 8 * ks, kph);
                const uint32_t bBase = sb + SM_B + ks * BLK + wn * 8192;
                kstep(aWarp + j * BLK, bBase, acc, a_kbh, b_rowoff, b_kbh, sx);
                if (lane == 0) MBAR_ARRIVE(sb + SM_KEMPTY + 8 * ks);
                if (++ks == KST) { ks = 0; kph ^= 1; }
            }

            // fold tile into running per-lane top-2 (ascending n per slot)
            #pragma unroll
            for (int mt = 0; mt < 2; mt++)
                #pragma unroll
                for (int half = 0; half < 2; half++) {
                    const int s = mt * 2 + half;
                    #pragma unroll
                    for (int nt = 0; nt < 8; nt++)
                        #pragma unroll
                        for (int j = 0; j < 2; j++) {
                            float v = acc[mt][nt][half * 2 + j];
                            int n = c * 128 + wn * 64 + nt * 8 + cq * 2 + j;
                            if (v > tv1[s]) { tv2[s] = tv1[s]; ti2[s] = ti1[s];
                                              tv1[s] = v; ti1[s] = n; }
                            else if (v > tv2[s]) { tv2[s] = v; ti2[s] = n; }
                        }
                }
        }

        // quad reduction (lanes cq=0..3 share each row)
        #pragma unroll
        for (int o = 1; o <= 2; o <<= 1)
            #pragma unroll
            for (int s = 0; s < 4; s++) {
                float w1 = __shfl_xor_sync(0xffffffffu, tv1[s], o);
                float w2 = __shfl_xor_sync(0xffffffffu, tv2[s], o);
                int k1 = __shfl_xor_sync(0xffffffffu, ti1[s], o);
                int k2 = __shfl_xor_sync(0xffffffffu, ti2[s], o);
                merge_top2(tv1[s], ti1[s], tv2[s], ti2[s], w1, k1, w2, k2);
            }
        if (cq == 0) {
            #pragma unroll
            for (int s = 0; s < 4; s++) {
                int row = wm * 32 + (s >> 1) * 16 + (s & 1) * 8 + g;
                sv2[row * 2 + wn] = make_uint4(__float_as_uint(tv1[s]),
                                               (uint32_t)ti1[s],
                                               __float_as_uint(tv2[s]),
                                               (uint32_t)ti2[s]);
            }
        }
    }
    __syncthreads();
    if (tid < MT) {
        uint4 a = sv2[tid * 2], b = sv2[tid * 2 + 1];
        float v1 = __uint_as_float(a.x), v2 = __uint_as_float(a.z);
        int i1 = (int)a.y, i2 = (int)a.w;
        merge_top2(v1, i1, v2, i2,
                   __uint_as_float(b.x), (int)b.y,
                   __uint_as_float(b.z), (int)b.w);
        g_top2[blockIdx.x * MT + tid] = make_int2(i1, i2);
    }
}

// ---------------------------------------------------------------------------
// Kernel 4: exact fp32 rescore of top-2 + projection/loss epilogue.
// Output (fp32): [x_q (B*D) | loss (1) | indices (B) | scalar (B)]
// ---------------------------------------------------------------------------
__global__ void epilogue_kernel(const float* __restrict__ X,
                                const float* __restrict__ E,
                                float* __restrict__ out) {
    const int gw   = (blockIdx.x * blockDim.x + threadIdx.x) >> 5;
    const int lane = threadIdx.x & 31;
    __shared__ float wsum[8];
    float contrib = 0.f;

    if (gw < B_) {
        const int b = gw;
        const int2 t2 = g_top2[b];
        const float4* xr = (const float4*)(X + (size_t)b * D_);
        const float4* c1 = (const float4*)(E + (size_t)t2.x * D_);
        const float4* c2 = (const float4*)(E + (size_t)t2.y * D_);
        float d1 = 0.f, d2 = 0.f, n1 = 0.f, n2 = 0.f, xsq = 0.f;
        float4 xv[2], e1[2], e2[2];
        #pragma unroll
        for (int r = 0; r < 2; r++) {
            int q = lane + r * 32;
            xv[r] = xr[q]; e1[r] = c1[q]; e2[r] = c2[q];
            d1 += xv[r].x*e1[r].x + xv[r].y*e1[r].y + xv[r].z*e1[r].z + xv[r].w*e1[r].w;
            d2 += xv[r].x*e2[r].x + xv[r].y*e2[r].y + xv[r].z*e2[r].z + xv[r].w*e2[r].w;
            n1 += e1[r].x*e1[r].x + e1[r].y*e1[r].y + e1[r].z*e1[r].z + e1[r].w*e1[r].w;
            n2 += e2[r].x*e2[r].x + e2[r].y*e2[r].y + e2[r].z*e2[r].z + e2[r].w*e2[r].w;
            xsq += xv[r].x*xv[r].x + xv[r].y*xv[r].y + xv[r].z*xv[r].z + xv[r].w*xv[r].w;
        }
        #pragma unroll
        for (int o = 16; o; o >>= 1) {
            d1 += __shfl_xor_sync(0xffffffffu, d1, o);
            d2 += __shfl_xor_sync(0xffffffffu, d2, o);
            n1 += __shfl_xor_sync(0xffffffffu, n1, o);
            n2 += __shfl_xor_sync(0xffffffffu, n2, o);
            xsq += __shfl_xor_sync(0xffffffffu, xsq, o);
        }
        const float s1 = d1 / fmaxf(sqrtf(n1), 1e-12f);
        const float s2 = d2 / fmaxf(sqrtf(n2), 1e-12f);
        const bool pick2 = (s2 > s1) || (s2 == s1 && t2.y < t2.x);
        const int   idx = pick2 ? t2.y : t2.x;
        const float dot = pick2 ? d2 : d1;
        const float nsq = pick2 ? n2 : n1;
        const float scalar = dot / (nsq + 1e-8f);

        float4* orow = (float4*)(out + (size_t)b * D_);
        #pragma unroll
        for (int r = 0; r < 2; r++) {
            int q = lane + r * 32;
            float4 cv = pick2 ? e2[r] : e1[r];
            float4 o;
            o.x = xv[r].x + (scalar * cv.x - xv[r].x);
            o.y = xv[r].y + (scalar * cv.y - xv[r].y);
            o.z = xv[r].z + (scalar * cv.z - xv[r].z);
            o.w = xv[r].w + (scalar * cv.w - xv[r].w);
            orow[q] = o;
        }
        if (lane == 0) {
            out[(size_t)B_ * D_ + 1 + b]      = (float)idx;
            out[(size_t)B_ * D_ + 1 + B_ + b] = scalar;
            const float nproj = fabsf(scalar) * sqrtf(nsq);
            const float nx = sqrtf(xsq);
            const float commit = (scalar * dot) /
                (fmaxf(nproj, 1e-8f) * fmaxf(nx, 1e-8f));
            contrib = 1.f - commit;
        }
    }
    const int w = threadIdx.x >> 5;
    if (lane == 0) wsum[w] = contrib;
    __syncthreads();
    if (threadIdx.x == 0) {
        float s = 0.f;
        #pragma unroll
        for (int i = 0; i < 8; i++) s += wsum[i];
        g_partial[blockIdx.x] = s;
    }
}

// ---------------------------------------------------------------------------
// Kernel 5: deterministic final loss reduction.
// ---------------------------------------------------------------------------
__global__ void loss_kernel(float* __restrict__ out) {
    __shared__ double red[256];
    const int t = threadIdx.x;
    double s = 0.0;
    for (int i = t; i < EPI_BLOCKS; i += 256) s += (double)g_partial[i];
    red[t] = s;
    __syncthreads();
    for (int o = 128; o; o >>= 1) {
        if (t < o) red[t] += red[t + o];
        __syncthreads();
    }
    if (t == 0) out[(size_t)B_ * D_] = (float)(0.25 * red[0] / (double)B_);
}

// ---------------------------------------------------------------------------
extern "C" void kernel_launch(void* const* d_in, const int* in_sizes, int n_in,
                              void* d_out, int out_size) {
    const float* X = (const float*)d_in[0];   // (32768, 256) fp32
    const float* E = (const float*)d_in[1];   // (8192, 256) fp32
    float* out = (float*)d_out;

    cudaFuncSetAttribute(mma_argmax_kernel,
                         cudaFuncAttributeMaxDynamicSharedMemorySize, SMEM_TOTAL);

    split_x_kernel<<<B_ * 32 / 256, 256>>>(X);
    split_cb_kernel<<<N_, 256>>>(E);
    mma_argmax_kernel<<<MTILES, 288, SMEM_TOTAL>>>();
    epilogue_kernel<<<EPI_BLOCKS, 256>>>(X, E, out);
    loss_kernel<<<1, 256>>>(out);
}